// round 2
// baseline (speedup 1.0000x reference)
#include <cuda_runtime.h>
#include <math.h>

typedef unsigned long long u64;

#define MSG_DIM 100
#define MEM_DIM 172
#define KDIM    272          // MSG_DIM + MEM_DIM
#define JPAD    176          // MEM_DIM padded
#define ROWS    32           // update rows per gru block
#define NTHREADS 192
#define XSTRIDE 36           // smem row stride in floats (144B, 16B aligned)
#define MASK_CAP (4u << 20)  // max nodes supported by overlap mask

// ---------------------------------------------------------------------------
// Persistent scratch: weights repacked K-major into gate planes (+ bias),
// plus updated-node mask used to overlap the passthrough copy with compute.
// ---------------------------------------------------------------------------
__device__ float g_Wr [KDIM    * JPAD];
__device__ float g_Wz [KDIM    * JPAD];
__device__ float g_Wni[MSG_DIM * JPAD];
__device__ float g_Wnh[MEM_DIM * JPAD];
__device__ float g_bias[4 * JPAD];
__device__ unsigned char g_mask[MASK_CAP];

// ---- packed fp32x2 helpers ------------------------------------------------
__device__ __forceinline__ u64 fma2(u64 b, u64 x, u64 c) {
    u64 d;
    asm("fma.rn.f32x2 %0, %1, %2, %3;" : "=l"(d) : "l"(b), "l"(x), "l"(c));
    return d;
}
__device__ __forceinline__ u64 dup2(float v) {
    u64 d; unsigned u = __float_as_uint(v);
    asm("mov.b64 %0, {%1, %1};" : "=l"(d) : "r"(u));
    return d;
}
__device__ __forceinline__ float2 unpack2(u64 d) {
    unsigned lo, hi;
    asm("mov.b64 {%0, %1}, %2;" : "=r"(lo), "=r"(hi) : "l"(d));
    return make_float2(__uint_as_float(lo), __uint_as_float(hi));
}

// ---------------------------------------------------------------------------
// Prep: repack W_ih [516,100], W_hh [516,172] into K-major planes + bias.
// ---------------------------------------------------------------------------
__global__ void prep_kernel(const float* __restrict__ W_ih,
                            const float* __restrict__ W_hh,
                            const float* __restrict__ b_ih,
                            const float* __restrict__ b_hh) {
    int idx = blockIdx.x * blockDim.x + threadIdx.x;
    if (idx < KDIM * JPAD) {
        int k = idx / JPAD;
        int j = idx - k * JPAD;
        float wr = 0.f, wz = 0.f;
        if (j < MEM_DIM) {
            if (k < MSG_DIM) {
                wr = W_ih[j * MSG_DIM + k];
                wz = W_ih[(MEM_DIM + j) * MSG_DIM + k];
            } else {
                int kk = k - MSG_DIM;
                wr = W_hh[j * MEM_DIM + kk];
                wz = W_hh[(MEM_DIM + j) * MEM_DIM + kk];
            }
        }
        g_Wr[k * JPAD + j] = wr;
        g_Wz[k * JPAD + j] = wz;
        if (k < MSG_DIM)
            g_Wni[k * JPAD + j] = (j < MEM_DIM) ? W_ih[(2 * MEM_DIM + j) * MSG_DIM + k] : 0.f;
        if (k < MEM_DIM)
            g_Wnh[k * JPAD + j] = (j < MEM_DIM) ? W_hh[(2 * MEM_DIM + j) * MEM_DIM + k] : 0.f;
    }
    if (idx < JPAD) {
        int j = idx;
        float br = 0.f, bz = 0.f, bi = 0.f, bh = 0.f;
        if (j < MEM_DIM) {
            br = b_ih[j]               + b_hh[j];
            bz = b_ih[MEM_DIM + j]     + b_hh[MEM_DIM + j];
            bi = b_ih[2 * MEM_DIM + j];
            bh = b_hh[2 * MEM_DIM + j];
        }
        g_bias[j]            = br;
        g_bias[JPAD + j]     = bz;
        g_bias[2 * JPAD + j] = bi;
        g_bias[3 * JPAD + j] = bh;
    }
}

__global__ void mask_kernel(const int* __restrict__ node_ids, int n_upd) {
    int i = blockIdx.x * blockDim.x + threadIdx.x;
    if (i < n_upd) {
        int nid = node_ids[i];
        if (nid >= 0 && (unsigned)nid < MASK_CAP) g_mask[nid] = 1;
    }
}

// Fallback plain copy (used only when mask can't be used)
__global__ void copy_kernel(const float* __restrict__ src, float* __restrict__ dst, long long n) {
    long long i = (long long)blockIdx.x * blockDim.x + threadIdx.x;
    long long n4 = n >> 2;
    if (i < n4) ((float4*)dst)[i] = ((const float4*)src)[i];
    long long tail = n & 3;
    if (i < tail) dst[n4 * 4 + i] = src[n4 * 4 + i];
}

// ---------------------------------------------------------------------------
// Fused kernel: every 4th CTA (up to copy_blocks) does the masked passthrough
// copy (DRAM-bound); the rest do gather + GRU GEMM + scatter (FMA-bound).
// ---------------------------------------------------------------------------
__global__ void __launch_bounds__(NTHREADS, 2)
fused_kernel(const int*   __restrict__ node_ids,
             const float* __restrict__ messages,
             const float* __restrict__ timestamps,
             const float* __restrict__ memory,
             const float* __restrict__ last_update,
             float*       __restrict__ out,
             int n_upd, long long n_nodes, int copy_blocks)
{
    const int tid = threadIdx.x;
    const int bid = blockIdx.x;
    const long long nmem = n_nodes * (long long)MEM_DIM;

    // ---------------- copy role ----------------
    if (((bid & 3) == 0) && ((bid >> 2) < copy_blocks)) {
        int cid = bid >> 2;
        long long n4 = nmem >> 2;          // MEM_DIM % 4 == 0
        long long stride = (long long)copy_blocks * NTHREADS;
        const float4* __restrict__ src = (const float4*)memory;
        float4* __restrict__ dst = (float4*)out;
        for (long long i = (long long)cid * NTHREADS + tid; i < n4; i += stride) {
            long long row = i / (MEM_DIM / 4);
            if (!g_mask[row]) dst[i] = src[i];
        }
        float* __restrict__ lo = out + nmem;
        for (long long i = (long long)cid * NTHREADS + tid; i < n_nodes; i += stride) {
            if (!g_mask[i]) lo[i] = last_update[i];
        }
        return;
    }

    // ---------------- gru role ----------------
    int before = (bid + 3) >> 2;
    if (before > copy_blocks) before = copy_blocks;
    const int gid  = bid - before;
    const int row0 = gid * ROWS;
    if (row0 >= n_upd) return;

    __shared__ __align__(16) float xT[KDIM][XSTRIDE];   // transposed [k][row]
    __shared__ int   s_nid[ROWS];
    __shared__ float s_ts [ROWS];

    if (tid < ROWS) {
        int r = row0 + tid;
        if (r < n_upd) { s_nid[tid] = node_ids[r]; s_ts[tid] = timestamps[r]; }
        else           { s_nid[tid] = -1;          s_ts[tid] = 0.f; }
    }
    __syncthreads();

    // Gather x = [msg | h] transposed into smem (coalesced global reads).
    for (int idx = tid; idx < ROWS * KDIM; idx += NTHREADS) {
        int r = idx / KDIM;
        int k = idx - r * KDIM;
        float v = 0.f;
        int nid = s_nid[r];
        if (nid >= 0) {
            v = (k < MSG_DIM)
              ? messages[(size_t)(row0 + r) * MSG_DIM + k]
              : memory  [(size_t)nid * MEM_DIM + (k - MSG_DIM)];
        }
        xT[k][r] = v;
    }
    __syncthreads();

    const int j = tid;
    if (j < JPAD) {
        u64 ar [ROWS / 2], az [ROWS / 2], ani[ROWS / 2], anh[ROWS / 2];
        const u64 z0 = dup2(0.f);
        #pragma unroll
        for (int p = 0; p < ROWS / 2; p++) { ar[p] = z0; az[p] = z0; ani[p] = z0; }

        const float* __restrict__ pr = g_Wr  + j;
        const float* __restrict__ pz = g_Wz  + j;
        const float* __restrict__ pi = g_Wni + j;
        const float* __restrict__ ph = g_Wnh + j;

        // Phase 1: k in [0,100) -> r, z, i_n (weights prefetched 1 iter ahead)
        float wr_c = __ldg(pr), wz_c = __ldg(pz), wn_c = __ldg(pi);
        for (int k = 0; k < MSG_DIM; k++) {
            float wr_n, wz_n, wn_n;
            int kn = k + 1;
            if (kn < MSG_DIM) {
                wr_n = __ldg(pr + kn * JPAD);
                wz_n = __ldg(pz + kn * JPAD);
                wn_n = __ldg(pi + kn * JPAD);
            } else {
                wr_n = __ldg(pr + MSG_DIM * JPAD);
                wz_n = __ldg(pz + MSG_DIM * JPAD);
                wn_n = __ldg(ph);
            }
            u64 wr2 = dup2(wr_c), wz2 = dup2(wz_c), wn2 = dup2(wn_c);
            const ulonglong2* __restrict__ xq = (const ulonglong2*)&xT[k][0];
            #pragma unroll
            for (int q = 0; q < ROWS / 4; q++) {
                ulonglong2 xv = xq[q];
                ar [2*q]   = fma2(wr2, xv.x, ar [2*q]);
                ar [2*q+1] = fma2(wr2, xv.y, ar [2*q+1]);
                az [2*q]   = fma2(wz2, xv.x, az [2*q]);
                az [2*q+1] = fma2(wz2, xv.y, az [2*q+1]);
                ani[2*q]   = fma2(wn2, xv.x, ani[2*q]);
                ani[2*q+1] = fma2(wn2, xv.y, ani[2*q+1]);
            }
            wr_c = wr_n; wz_c = wz_n; wn_c = wn_n;
        }

        #pragma unroll
        for (int p = 0; p < ROWS / 2; p++) anh[p] = z0;

        // Phase 2: k in [100,272) -> r, z, h_n
        for (int k = MSG_DIM; k < KDIM; k++) {
            float wr_n, wz_n, wn_n;
            int kn = k + 1;
            if (kn < KDIM) {
                wr_n = __ldg(pr + kn * JPAD);
                wz_n = __ldg(pz + kn * JPAD);
                wn_n = __ldg(ph + (kn - MSG_DIM) * JPAD);
            } else {
                wr_n = 0.f; wz_n = 0.f; wn_n = 0.f;
            }
            u64 wr2 = dup2(wr_c), wz2 = dup2(wz_c), wn2 = dup2(wn_c);
            const ulonglong2* __restrict__ xq = (const ulonglong2*)&xT[k][0];
            #pragma unroll
            for (int q = 0; q < ROWS / 4; q++) {
                ulonglong2 xv = xq[q];
                ar [2*q]   = fma2(wr2, xv.x, ar [2*q]);
                ar [2*q+1] = fma2(wr2, xv.y, ar [2*q+1]);
                az [2*q]   = fma2(wz2, xv.x, az [2*q]);
                az [2*q+1] = fma2(wz2, xv.y, az [2*q+1]);
                anh[2*q]   = fma2(wn2, xv.x, anh[2*q]);
                anh[2*q+1] = fma2(wn2, xv.y, anh[2*q+1]);
            }
            wr_c = wr_n; wz_c = wz_n; wn_c = wn_n;
        }

        if (j < MEM_DIM) {
            const float br = g_bias[j];
            const float bz = g_bias[JPAD + j];
            const float bi = g_bias[2 * JPAD + j];
            const float bh = g_bias[3 * JPAD + j];

            #pragma unroll
            for (int p = 0; p < ROWS / 2; p++) {
                float2 arv = unpack2(ar [p]);
                float2 azv = unpack2(az [p]);
                float2 aiv = unpack2(ani[p]);
                float2 ahv = unpack2(anh[p]);
                #pragma unroll
                for (int s = 0; s < 2; s++) {
                    int r = 2 * p + s;
                    int nid = s_nid[r];
                    if (nid < 0) continue;
                    float a_r = (s ? arv.y : arv.x) + br;
                    float a_z = (s ? azv.y : azv.x) + bz;
                    float a_i = (s ? aiv.y : aiv.x) + bi;
                    float a_h = (s ? ahv.y : ahv.x) + bh;
                    float rg = 1.f / (1.f + expf(-a_r));
                    float zg = 1.f / (1.f + expf(-a_z));
                    float ng = tanhf(a_i + rg * a_h);
                    float h_old = xT[MSG_DIM + j][r];
                    out[(size_t)nid * MEM_DIM + j] = (1.f - zg) * ng + zg * h_old;
                }
            }
        }
    }

    if (tid < ROWS && s_nid[tid] >= 0) {
        out[(size_t)n_nodes * MEM_DIM + s_nid[tid]] = s_ts[tid];
    }
}

// ---------------------------------------------------------------------------
extern "C" void kernel_launch(void* const* d_in, const int* in_sizes, int n_in,
                              void* d_out, int out_size) {
    const int*   node_ids    = (const int*)  d_in[0];
    const float* messages    = (const float*)d_in[1];
    const float* timestamps  = (const float*)d_in[2];
    const float* memory      = (const float*)d_in[3];
    const float* last_update = (const float*)d_in[4];
    const float* W_ih        = (const float*)d_in[5];
    const float* W_hh        = (const float*)d_in[6];
    const float* b_ih        = (const float*)d_in[7];
    const float* b_hh        = (const float*)d_in[8];
    float* out = (float*)d_out;

    const int       n_upd   = in_sizes[0];
    const long long n_nodes = in_sizes[4];
    const long long nmem    = n_nodes * (long long)MEM_DIM;

    prep_kernel<<<(KDIM * JPAD + 255) / 256, 256>>>(W_ih, W_hh, b_ih, b_hh);

    int gru_blocks = (n_upd + ROWS - 1) / ROWS;
    bool merged = (n_nodes <= (long long)MASK_CAP) && (gru_blocks >= 8);

    if (merged) {
        mask_kernel<<<(n_upd + 255) / 256, 256>>>(node_ids, n_upd);
        int copy_blocks = gru_blocks / 3;           // every 4th CTA is copy
        if (copy_blocks < 1) copy_blocks = 1;
        fused_kernel<<<gru_blocks + copy_blocks, NTHREADS>>>(
            node_ids, messages, timestamps, memory, last_update, out,
            n_upd, n_nodes, copy_blocks);
    } else {
        // fallback: plain copy, then gru (no copy blocks, no mask dependence)
        long long n4 = (nmem + 3) >> 2;
        copy_kernel<<<(unsigned)((n4 + 255) / 256), 256>>>(memory, out, nmem);
        long long n4b = (n_nodes + 3) >> 2;
        copy_kernel<<<(unsigned)((n4b + 255) / 256), 256>>>(last_update, out + nmem, n_nodes);
        if (n_upd > 0) {
            fused_kernel<<<gru_blocks, NTHREADS>>>(
                node_ids, messages, timestamps, memory, last_update, out,
                n_upd, n_nodes, 0);
        }
    }
}